// round 1
// baseline (speedup 1.0000x reference)
#include <cuda_runtime.h>
#include <math.h>

#define NROWS 65536
#define DIM   512
#define KCLS  512
#define LISTCAP 768   // max class population; 512-class multinomial of 65536 draws: mean 128, sd ~11 -> 768 is ~57 sigma

// -------- scratch (device globals; no runtime allocation) --------
__device__ float g_emb[(size_t)NROWS * DIM];   // normalized embeddings, 134MB
__device__ float g_sums[KCLS * DIM];           // per-class sums of normalized rows
__device__ float g_cent[KCLS * DIM];           // centroids = sums / max(cnt,1)
__device__ float g_cnt[KCLS];                  // class counts (float)
__device__ float g_snorm2[KCLS];               // ||sums_k||^2
__device__ float g_rowfix[NROWS];              // logit value at the label column per row
__device__ int   g_ccount[KCLS];               // int class counters (list build)
__device__ int   g_lists[KCLS * LISTCAP];      // member row indices per class

// -------- kernel A: zero counters + output --------
__global__ void k_zero(float* out) {
    int t = blockIdx.x * blockDim.x + threadIdx.x;
    if (t < KCLS) g_ccount[t] = 0;
    if (t == 0) out[0] = 0.0f;
}

// -------- kernel B: L2-normalize rows (warp per row) --------
__global__ void k_norm(const float* __restrict__ x) {
    int row  = blockIdx.x * 8 + (threadIdx.x >> 5);
    int lane = threadIdx.x & 31;
    const float4* src = (const float4*)(x + (size_t)row * DIM);
    float4 v[4];
    float ss = 0.0f;
#pragma unroll
    for (int q = 0; q < 4; q++) {
        v[q] = src[lane + 32 * q];
        ss += v[q].x * v[q].x + v[q].y * v[q].y + v[q].z * v[q].z + v[q].w * v[q].w;
    }
#pragma unroll
    for (int o = 16; o >= 1; o >>= 1) ss += __shfl_xor_sync(0xffffffffu, ss, o);
    float inv = 1.0f / fmaxf(sqrtf(ss), 1e-12f);
    float4* dst = (float4*)(g_emb + (size_t)row * DIM);
#pragma unroll
    for (int q = 0; q < 4; q++) {
        float4 w = v[q];
        w.x *= inv; w.y *= inv; w.z *= inv; w.w *= inv;
        dst[lane + 32 * q] = w;
    }
}

// -------- kernel B1: build per-class member lists --------
__global__ void k_lists(const int* __restrict__ labels) {
    int i = blockIdx.x * blockDim.x + threadIdx.x;
    if (i < NROWS) {
        int lab = labels[i];
        int pos = atomicAdd(&g_ccount[lab], 1);
        if (pos < LISTCAP) g_lists[lab * LISTCAP + pos] = i;
    }
}

// -------- kernel B2: class sums, centroids, ||s||^2 (block per class) --------
__global__ void k_csum() {
    int k = blockIdx.x;
    int t = threadIdx.x;            // 256 threads; cols t and t+256
    int cnt = g_ccount[k];
    const int* lst = g_lists + k * LISTCAP;
    float a0 = 0.0f, a1 = 0.0f;
    int m = 0;
    for (; m + 4 <= cnt; m += 4) {
        int r0 = lst[m], r1 = lst[m + 1], r2 = lst[m + 2], r3 = lst[m + 3];
        float x0 = g_emb[(size_t)r0 * DIM + t],       y0 = g_emb[(size_t)r0 * DIM + t + 256];
        float x1 = g_emb[(size_t)r1 * DIM + t],       y1 = g_emb[(size_t)r1 * DIM + t + 256];
        float x2 = g_emb[(size_t)r2 * DIM + t],       y2 = g_emb[(size_t)r2 * DIM + t + 256];
        float x3 = g_emb[(size_t)r3 * DIM + t],       y3 = g_emb[(size_t)r3 * DIM + t + 256];
        a0 += x0 + x1 + x2 + x3;
        a1 += y0 + y1 + y2 + y3;
    }
    for (; m < cnt; m++) {
        int r = lst[m];
        a0 += g_emb[(size_t)r * DIM + t];
        a1 += g_emb[(size_t)r * DIM + t + 256];
    }
    float c = (float)cnt;
    if (t == 0) g_cnt[k] = c;
    float inv = 1.0f / fmaxf(c, 1.0f);
    g_sums[k * DIM + t]       = a0;
    g_sums[k * DIM + t + 256] = a1;
    g_cent[k * DIM + t]       = a0 * inv;
    g_cent[k * DIM + t + 256] = a1 * inv;

    __shared__ float red[256];
    red[t] = a0 * a0 + a1 * a1;
    __syncthreads();
    for (int s = 128; s > 0; s >>= 1) {
        if (t < s) red[t] += red[t + s];
        __syncthreads();
    }
    if (t == 0) g_snorm2[k] = red[0];
}

// -------- kernel D: per-row label-column logit (warp per row) --------
// t = dot(e, sums[label]); own = (t-1)/max(||s-e||, denom*eps) since l2norm((s-e)/denom)
// uses ||s-e||^2 = ||s||^2 - 2t + 1  (||e|| = 1)
__global__ void k_rowfix(const int* __restrict__ labels,
                         const float* __restrict__ wp, const float* __restrict__ bp) {
    int row  = blockIdx.x * 8 + (threadIdx.x >> 5);
    int lane = threadIdx.x & 31;
    int lab = labels[row];
    const float4* e = (const float4*)(g_emb + (size_t)row * DIM);
    const float4* s = (const float4*)(g_sums + (size_t)lab * DIM);
    float t = 0.0f;
#pragma unroll
    for (int q = 0; q < 4; q++) {
        float4 ev = e[lane + 32 * q];
        float4 sv = s[lane + 32 * q];
        t += ev.x * sv.x + ev.y * sv.y + ev.z * sv.z + ev.w * sv.w;
    }
#pragma unroll
    for (int o = 16; o >= 1; o >>= 1) t += __shfl_xor_sync(0xffffffffu, t, o);
    if (lane == 0) {
        float cnt = g_cnt[lab];
        float sn  = g_snorm2[lab];
        float wv = fmaxf(wp[0], 1e-6f);
        float bv = bp[0];
        float simlab;
        if (cnt > 1.0f) {
            float denom = fmaxf(cnt - 1.0f, 1.0f);
            float num = (t - 1.0f) / denom;
            float nrm = sqrtf(fmaxf(sn - 2.0f * t + 1.0f, 0.0f)) / denom;
            simlab = num / fmaxf(nrm, 1e-12f);
        } else {
            simlab = t / fmaxf(cnt, 1.0f);     // cur = sims[i, label] for singleton class
        }
        g_rowfix[row] = fmaf(wv, simlab, bv);
    }
}

// -------- kernel E: fused GEMM (E @ C^T) + online logsumexp + loss --------
// 128x128 tile per chunk, 4 class chunks, BK=8 double-buffered, 8x8 register tile.
__global__ void __launch_bounds__(256, 2)
k_main(const int* __restrict__ labels,
       const float* __restrict__ wp, const float* __restrict__ bp,
       float* __restrict__ out) {
    __shared__ float As[2][8][128];
    __shared__ float Bs[2][8][128];
    __shared__ float rowM[128];
    __shared__ float rowS[128];

    const int tid = threadIdx.x;
    const int tx = tid & 15;
    const int ty = tid >> 4;
    const int block_row = blockIdx.x * 128;

    const int lrow = tid >> 1;          // 0..127 (tile row to load)
    const int lcol = (tid & 1) << 2;    // 0 or 4 (k-offset within BK)

    const float wv = fmaxf(wp[0], 1e-6f);
    const float bv = bp[0];

    if (tid < 128) { rowM[tid] = -INFINITY; rowS[tid] = 0.0f; }

    const float* Abase = g_emb + (size_t)(block_row + lrow) * DIM + lcol;

    for (int chunk = 0; chunk < 4; ++chunk) {
        const int col0 = chunk * 128;
        const float* Bbase = g_cent + (size_t)(col0 + lrow) * DIM + lcol;

        float acc[8][8];
#pragma unroll
        for (int i = 0; i < 8; i++)
#pragma unroll
            for (int j = 0; j < 8; j++) acc[i][j] = 0.0f;

        __syncthreads();  // safe to overwrite tiles from previous chunk
        {
            float4 a4 = *(const float4*)(Abase);
            float4 b4 = *(const float4*)(Bbase);
            As[0][lcol + 0][lrow] = a4.x; As[0][lcol + 1][lrow] = a4.y;
            As[0][lcol + 2][lrow] = a4.z; As[0][lcol + 3][lrow] = a4.w;
            Bs[0][lcol + 0][lrow] = b4.x; Bs[0][lcol + 1][lrow] = b4.y;
            Bs[0][lcol + 2][lrow] = b4.z; Bs[0][lcol + 3][lrow] = b4.w;
        }
        __syncthreads();

        int buf = 0;
        for (int kb = 0; kb < 64; ++kb) {
            float4 a4n, b4n;
            if (kb < 63) {
                a4n = *(const float4*)(Abase + (kb + 1) * 8);
                b4n = *(const float4*)(Bbase + (kb + 1) * 8);
            }
#pragma unroll
            for (int k = 0; k < 8; k++) {
                float4 av0 = *(const float4*)&As[buf][k][ty * 4];
                float4 av1 = *(const float4*)&As[buf][k][64 + ty * 4];
                float4 bv0 = *(const float4*)&Bs[buf][k][tx * 4];
                float4 bv1 = *(const float4*)&Bs[buf][k][64 + tx * 4];
                float a[8] = {av0.x, av0.y, av0.z, av0.w, av1.x, av1.y, av1.z, av1.w};
                float b[8] = {bv0.x, bv0.y, bv0.z, bv0.w, bv1.x, bv1.y, bv1.z, bv1.w};
#pragma unroll
                for (int i = 0; i < 8; i++)
#pragma unroll
                    for (int j = 0; j < 8; j++)
                        acc[i][j] = fmaf(a[i], b[j], acc[i][j]);
            }
            if (kb < 63) {
                int nb = buf ^ 1;
                As[nb][lcol + 0][lrow] = a4n.x; As[nb][lcol + 1][lrow] = a4n.y;
                As[nb][lcol + 2][lrow] = a4n.z; As[nb][lcol + 3][lrow] = a4n.w;
                Bs[nb][lcol + 0][lrow] = b4n.x; Bs[nb][lcol + 1][lrow] = b4n.y;
                Bs[nb][lcol + 2][lrow] = b4n.z; Bs[nb][lcol + 3][lrow] = b4n.w;
                __syncthreads();
                buf = nb;
            }
        }

        // epilogue: per-row online LSE over this 128-class chunk
#pragma unroll
        for (int i = 0; i < 8; i++) {
            int r = (i < 4) ? (ty * 4 + i) : (64 + ty * 4 + (i - 4));
            int grow = block_row + r;
            int lab  = labels[grow];
            float rf = g_rowfix[grow];
            float vals[8];
            float lmax = -INFINITY;
#pragma unroll
            for (int j = 0; j < 8; j++) {
                int gcol = col0 + ((j < 4) ? (tx * 4 + j) : (64 + tx * 4 + (j - 4)));
                float lg = (gcol == lab) ? rf : fmaf(wv, acc[i][j], bv);
                vals[j] = lg;
                lmax = fmaxf(lmax, lg);
            }
#pragma unroll
            for (int o = 8; o >= 1; o >>= 1)
                lmax = fmaxf(lmax, __shfl_xor_sync(0xffffffffu, lmax, o, 16));
            float lsum = 0.0f;
#pragma unroll
            for (int j = 0; j < 8; j++) lsum += __expf(vals[j] - lmax);
#pragma unroll
            for (int o = 8; o >= 1; o >>= 1)
                lsum += __shfl_xor_sync(0xffffffffu, lsum, o, 16);
            if (tx == 0) {   // one thread per row merges the chunk into running state
                float mo = rowM[r];
                float mn = fmaxf(mo, lmax);
                rowS[r] = rowS[r] * __expf(mo - mn) + lsum * __expf(lmax - mn);
                rowM[r] = mn;
            }
        }
    }

    __syncthreads();
    float part = 0.0f;
    if (tid < 128) {
        int grow = block_row + tid;
        // loss_i = logsumexp_i - logit_i[label_i]
        part = rowM[tid] + logf(rowS[tid]) - g_rowfix[grow];
    }
#pragma unroll
    for (int o = 16; o >= 1; o >>= 1) part += __shfl_xor_sync(0xffffffffu, part, o);
    if (tid < 128 && (tid & 31) == 0)
        atomicAdd(out, part * (1.0f / (float)NROWS));
}

extern "C" void kernel_launch(void* const* d_in, const int* in_sizes, int n_in,
                              void* d_out, int out_size) {
    const float* emb    = (const float*)d_in[0];
    const int*   labels = (const int*)d_in[1];
    const float* wp     = (const float*)d_in[2];
    const float* bp     = (const float*)d_in[3];
    float* out = (float*)d_out;

    k_zero<<<1, 512>>>(out);
    k_norm<<<NROWS / 8, 256>>>(emb);
    k_lists<<<NROWS / 256, 256>>>(labels);
    k_csum<<<KCLS, 256>>>();
    k_rowfix<<<NROWS / 8, 256>>>(labels, wp, bp);
    k_main<<<NROWS / 128, 256>>>(labels, wp, bp, out);
}

// round 5
// speedup vs baseline: 3.5226x; 3.5226x over previous
#include <cuda_runtime.h>
#include <cuda_bf16.h>
#include <math.h>
#include <stdint.h>

#define NROWS 65536
#define DIM   512
#define KCLS  512
#define LISTCAP 768

// -------- scratch (device globals; no runtime allocation) --------
__device__ float          g_emb[(size_t)NROWS * DIM];    // normalized embeddings fp32
__device__ __nv_bfloat16  g_embh[(size_t)NROWS * DIM];   // normalized embeddings bf16
__device__ float          g_sums[KCLS * DIM];            // per-class sums (fp32)
__device__ __nv_bfloat16  g_centh[KCLS * DIM];           // centroids bf16 (GEMM B)
__device__ float          g_cnt[KCLS];
__device__ float          g_snorm2[KCLS];
__device__ float          g_rowfix[NROWS];               // exact label-column logit per row
__device__ int            g_ccount[KCLS];
__device__ int            g_lists[KCLS * LISTCAP];

// ================= helpers =================
__device__ __forceinline__ uint32_t smem_u32(const void* p) {
    uint32_t a;
    asm("{ .reg .u64 t; cvta.to.shared.u64 t, %1; cvt.u32.u64 %0, t; }" : "=r"(a) : "l"(p));
    return a;
}
#define CP16(dst, src)  asm volatile("cp.async.cg.shared.global [%0], [%1], 16;" :: "r"(dst), "l"(src) : "memory")
#define CP_COMMIT()     asm volatile("cp.async.commit_group;" ::: "memory")
#define CP_WAIT0()      asm volatile("cp.async.wait_group 0;" ::: "memory")
#define CP_WAIT1()      asm volatile("cp.async.wait_group 1;" ::: "memory")

#define LDSM4(r0, r1, r2, r3, addr)                                           \
    asm volatile("ldmatrix.sync.aligned.m8n8.x4.shared.b16 {%0,%1,%2,%3}, [%4];" \
        : "=r"(r0), "=r"(r1), "=r"(r2), "=r"(r3) : "r"(addr))

#define MMA16816(c, a, b0, b1)                                                \
    asm volatile("mma.sync.aligned.m16n8k16.row.col.f32.bf16.bf16.f32 "       \
        "{%0,%1,%2,%3}, {%4,%5,%6,%7}, {%8,%9}, {%0,%1,%2,%3};"               \
        : "+f"((c)[0]), "+f"((c)[1]), "+f"((c)[2]), "+f"((c)[3])              \
        : "r"((a)[0]), "r"((a)[1]), "r"((a)[2]), "r"((a)[3]), "r"(b0), "r"(b1))

// ================= prep kernels (unchanged, passing) =================
__global__ void k_zero(float* out) {
    int t = blockIdx.x * blockDim.x + threadIdx.x;
    if (t < KCLS) g_ccount[t] = 0;
    if (t == 0) out[0] = 0.0f;
}

__global__ void k_norm(const float* __restrict__ x) {
    int row  = blockIdx.x * 8 + (threadIdx.x >> 5);
    int lane = threadIdx.x & 31;
    const float4* src = (const float4*)(x + (size_t)row * DIM);
    float4 v[4];
    float ss = 0.0f;
#pragma unroll
    for (int q = 0; q < 4; q++) {
        v[q] = src[lane + 32 * q];
        ss += v[q].x * v[q].x + v[q].y * v[q].y + v[q].z * v[q].z + v[q].w * v[q].w;
    }
#pragma unroll
    for (int o = 16; o >= 1; o >>= 1) ss += __shfl_xor_sync(0xffffffffu, ss, o);
    float inv = 1.0f / fmaxf(sqrtf(ss), 1e-12f);
    float4* dst = (float4*)(g_emb + (size_t)row * DIM);
    __nv_bfloat162* dsth = (__nv_bfloat162*)(g_embh + (size_t)row * DIM);
#pragma unroll
    for (int q = 0; q < 4; q++) {
        float4 w = v[q];
        w.x *= inv; w.y *= inv; w.z *= inv; w.w *= inv;
        dst[lane + 32 * q] = w;
        int i = lane + 32 * q;
        dsth[2 * i]     = __floats2bfloat162_rn(w.x, w.y);
        dsth[2 * i + 1] = __floats2bfloat162_rn(w.z, w.w);
    }
}

__global__ void k_lists(const int* __restrict__ labels) {
    int i = blockIdx.x * blockDim.x + threadIdx.x;
    if (i < NROWS) {
        int lab = labels[i];
        int pos = atomicAdd(&g_ccount[lab], 1);
        if (pos < LISTCAP) g_lists[lab * LISTCAP + pos] = i;
    }
}

__global__ void k_csum() {
    int k = blockIdx.x;
    int t = threadIdx.x;
    int cnt = g_ccount[k];
    const int* lst = g_lists + k * LISTCAP;
    float a0 = 0.0f, a1 = 0.0f;
    int m = 0;
    for (; m + 4 <= cnt; m += 4) {
        int r0 = lst[m], r1 = lst[m + 1], r2 = lst[m + 2], r3 = lst[m + 3];
        a0 += g_emb[(size_t)r0 * DIM + t] + g_emb[(size_t)r1 * DIM + t]
            + g_emb[(size_t)r2 * DIM + t] + g_emb[(size_t)r3 * DIM + t];
        a1 += g_emb[(size_t)r0 * DIM + t + 256] + g_emb[(size_t)r1 * DIM + t + 256]
            + g_emb[(size_t)r2 * DIM + t + 256] + g_emb[(size_t)r3 * DIM + t + 256];
    }
    for (; m < cnt; m++) {
        int r = lst[m];
        a0 += g_emb[(size_t)r * DIM + t];
        a1 += g_emb[(size_t)r * DIM + t + 256];
    }
    float c = (float)cnt;
    if (t == 0) g_cnt[k] = c;
    float inv = 1.0f / fmaxf(c, 1.0f);
    g_sums[k * DIM + t]       = a0;
    g_sums[k * DIM + t + 256] = a1;
    g_centh[k * DIM + t]       = __float2bfloat16(a0 * inv);
    g_centh[k * DIM + t + 256] = __float2bfloat16(a1 * inv);

    __shared__ float red[256];
    red[t] = a0 * a0 + a1 * a1;
    __syncthreads();
    for (int s = 128; s > 0; s >>= 1) {
        if (t < s) red[t] += red[t + s];
        __syncthreads();
    }
    if (t == 0) g_snorm2[k] = red[0];
}

__global__ void k_rowfix(const int* __restrict__ labels,
                         const float* __restrict__ wp, const float* __restrict__ bp) {
    int row  = blockIdx.x * 8 + (threadIdx.x >> 5);
    int lane = threadIdx.x & 31;
    int lab = labels[row];
    const float4* e = (const float4*)(g_emb + (size_t)row * DIM);
    const float4* s = (const float4*)(g_sums + (size_t)lab * DIM);
    float t = 0.0f;
#pragma unroll
    for (int q = 0; q < 4; q++) {
        float4 ev = e[lane + 32 * q];
        float4 sv = s[lane + 32 * q];
        t += ev.x * sv.x + ev.y * sv.y + ev.z * sv.z + ev.w * sv.w;
    }
#pragma unroll
    for (int o = 16; o >= 1; o >>= 1) t += __shfl_xor_sync(0xffffffffu, t, o);
    if (lane == 0) {
        float cnt = g_cnt[lab];
        float sn  = g_snorm2[lab];
        float wv = fmaxf(wp[0], 1e-6f);
        float bv = bp[0];
        float simlab;
        if (cnt > 1.0f) {
            float denom = fmaxf(cnt - 1.0f, 1.0f);
            float num = (t - 1.0f) / denom;
            float nrm = sqrtf(fmaxf(sn - 2.0f * t + 1.0f, 0.0f)) / denom;
            simlab = num / fmaxf(nrm, 1e-12f);
        } else {
            simlab = t / fmaxf(cnt, 1.0f);
        }
        g_rowfix[row] = fmaf(wv, simlab, bv);
    }
}

// ================= main: bf16 mma.sync GEMM + fused LSE =================
// dyn smem: [0, 128KB) A resident tile (128 rows x 512 bf16, swizzled)
//           [128KB, 160KB) B double buffer (2 x 128 classes x 64 bf16)
#define SM_B_OFF 131072
#define SMEM_BYTES (131072 + 2 * 16384)

__global__ void __launch_bounds__(256, 1)
k_main_mma(const int* __restrict__ labels,
           const float* __restrict__ wp, const float* __restrict__ bp,
           float* __restrict__ out) {
    extern __shared__ char smem[];
    const uint32_t smA = smem_u32(smem);
    const uint32_t smB = smA + SM_B_OFF;

    const int tid = threadIdx.x;
    const int wid = tid >> 5;
    const int l   = tid & 31;
    const int wm  = wid >> 1;        // 0..3 (M)
    const int wn  = wid & 1;         // 0..1 (N half)
    const int block_row = blockIdx.x * 128;

    const float wv = fmaxf(wp[0], 1e-6f);
    const float bv = bp[0];

    // ---- load resident A tile (128 x 512 bf16), 16B chunks, XOR swizzle ----
#pragma unroll
    for (int it = 0; it < 32; it++) {
        uint32_t u = it * 256 + tid;
        uint32_t r = u >> 6, ch = u & 63;
        CP16(smA + r * 1024 + ((ch ^ (r & 7)) << 4),
             g_embh + (size_t)(block_row + r) * DIM + ch * 8);
    }
    CP_COMMIT();

    // ---- per-thread row metadata (rows this thread's acc fragment covers) ----
    int lab_[2][2];
    float rf_[2][2];
#pragma unroll
    for (int mt = 0; mt < 2; mt++)
#pragma unroll
        for (int h = 0; h < 2; h++) {
            int rr = block_row + wm * 32 + mt * 16 + (l >> 2) + h * 8;
            lab_[mt][h] = labels[rr];
            rf_[mt][h]  = g_rowfix[rr];
        }

    float run_m[2][2], run_s[2][2];
#pragma unroll
    for (int mt = 0; mt < 2; mt++)
#pragma unroll
        for (int h = 0; h < 2; h++) { run_m[mt][h] = -INFINITY; run_s[mt][h] = 0.0f; }

    for (int chunk = 0; chunk < 4; chunk++) {
        const int c0 = chunk * 128;

        // preload B stage 0 of this chunk
#pragma unroll
        for (int it = 0; it < 4; it++) {
            uint32_t u = it * 256 + tid;
            uint32_t nr = u >> 3, k16 = u & 7;
            CP16(smB + nr * 128 + ((k16 ^ (nr & 7)) << 4),
                 g_centh + (size_t)(c0 + nr) * DIM + k16 * 8);
        }
        CP_COMMIT();

        float acc[2][8][4];
#pragma unroll
        for (int mt = 0; mt < 2; mt++)
#pragma unroll
            for (int nt = 0; nt < 8; nt++)
#pragma unroll
                for (int c = 0; c < 4; c++) acc[mt][nt][c] = 0.0f;

        for (int kb = 0; kb < 8; kb++) {
            const uint32_t buf = (uint32_t)(kb & 1);
            if (kb < 7) {
                const uint32_t nb = buf ^ 1;
#pragma unroll
                for (int it = 0; it < 4; it++) {
                    uint32_t u = it * 256 + tid;
                    uint32_t nr = u >> 3, k16 = u & 7;
                    CP16(smB + nb * 16384 + nr * 128 + ((k16 ^ (nr & 7)) << 4),
                         g_centh + (size_t)(c0 + nr) * DIM + (kb + 1) * 64 + k16 * 8);
                }
                CP_COMMIT();
                CP_WAIT1();
            } else {
                CP_WAIT0();
            }
            __syncthreads();

#pragma unroll
            for (int step = 0; step < 4; step++) {
                uint32_t a[2][4];
#pragma unroll
                for (int mt = 0; mt < 2; mt++) {
                    uint32_t r = wm * 32 + mt * 16 + (l & 15);
                    uint32_t chA = kb * 8 + step * 2 + (l >> 4);
                    LDSM4(a[mt][0], a[mt][1], a[mt][2], a[mt][3],
                          smA + r * 1024 + ((chA ^ (r & 7)) << 4));
                }
                uint32_t bf[8][2];
#pragma unroll
                for (int np = 0; np < 4; np++) {
                    uint32_t n = wn * 64 + np * 16 + (l & 7) + ((l >> 4) & 1) * 8;
                    uint32_t chB = step * 2 + ((l >> 3) & 1);
                    uint32_t r0, r1, r2, r3;
                    LDSM4(r0, r1, r2, r3,
                          smB + buf * 16384 + n * 128 + ((chB ^ (n & 7)) << 4));
                    bf[2 * np][0] = r0;     bf[2 * np][1] = r1;
                    bf[2 * np + 1][0] = r2; bf[2 * np + 1][1] = r3;
                }
#pragma unroll
                for (int mt = 0; mt < 2; mt++)
#pragma unroll
                    for (int nt = 0; nt < 8; nt++)
                        MMA16816(acc[mt][nt], a[mt], bf[nt][0], bf[nt][1]);
            }
            __syncthreads();
        }

        // ---- chunk epilogue: per-row LSE over this warp's 64 cols ----
#pragma unroll
        for (int mt = 0; mt < 2; mt++) {
#pragma unroll
            for (int h = 0; h < 2; h++) {
                float v[16];
                float cm = -INFINITY;
#pragma unroll
                for (int nt = 0; nt < 8; nt++)
#pragma unroll
                    for (int cc = 0; cc < 2; cc++) {
                        int col = c0 + wn * 64 + nt * 8 + ((l & 3) << 1) + cc;
                        float raw = acc[mt][nt][h * 2 + cc];
                        float lg = (col == lab_[mt][h]) ? rf_[mt][h]
                                                        : fmaf(wv, raw, bv);
                        v[nt * 2 + cc] = lg;
                        cm = fmaxf(cm, lg);
                    }
#pragma unroll
                for (int o = 1; o <= 2; o <<= 1)
                    cm = fmaxf(cm, __shfl_xor_sync(0xffffffffu, cm, o));
                float cs = 0.0f;
#pragma unroll
                for (int j = 0; j < 16; j++) cs += __expf(v[j] - cm);
#pragma unroll
                for (int o = 1; o <= 2; o <<= 1)
                    cs += __shfl_xor_sync(0xffffffffu, cs, o);
                float mo = run_m[mt][h];
                float mn = fmaxf(mo, cm);
                run_s[mt][h] = run_s[mt][h] * __expf(mo - mn) + cs * __expf(cm - mn);
                run_m[mt][h] = mn;
            }
        }
    }

    // ---- merge the two N-half warps per row, compute loss ----
    __syncthreads();
    float* marr = (float*)smem;          // reuse A region (dead now)
    float* sarr = marr + 128;
    if (wn == 0 && (l & 3) == 0) {
#pragma unroll
        for (int mt = 0; mt < 2; mt++)
#pragma unroll
            for (int h = 0; h < 2; h++) {
                int rr = wm * 32 + mt * 16 + h * 8 + (l >> 2);
                marr[rr] = run_m[mt][h];
                sarr[rr] = run_s[mt][h];
            }
    }
    __syncthreads();
    float loss = 0.0f;
    if (wn == 1 && (l & 3) == 0) {
#pragma unroll
        for (int mt = 0; mt < 2; mt++)
#pragma unroll
            for (int h = 0; h < 2; h++) {
                int rr = wm * 32 + mt * 16 + h * 8 + (l >> 2);
                float m0 = marr[rr], s0 = sarr[rr];
                float m1 = run_m[mt][h], s1 = run_s[mt][h];
                float mn = fmaxf(m0, m1);
                float ssum = s0 * __expf(m0 - mn) + s1 * __expf(m1 - mn);
                loss += mn + logf(ssum) - rf_[mt][h];
            }
    }
#pragma unroll
    for (int o = 16; o >= 1; o >>= 1) loss += __shfl_xor_sync(0xffffffffu, loss, o);
    if (wn == 1 && l == 0) atomicAdd(out, loss * (1.0f / (float)NROWS));
}

extern "C" void kernel_launch(void* const* d_in, const int* in_sizes, int n_in,
                              void* d_out, int out_size) {
    const float* emb    = (const float*)d_in[0];
    const int*   labels = (const int*)d_in[1];
    const float* wp     = (const float*)d_in[2];
    const float* bp     = (const float*)d_in[3];
    float* out = (float*)d_out;

    cudaFuncSetAttribute(k_main_mma, cudaFuncAttributeMaxDynamicSharedMemorySize, SMEM_BYTES);

    k_zero<<<1, 512>>>(out);
    k_norm<<<NROWS / 8, 256>>>(emb);
    k_lists<<<NROWS / 256, 256>>>(labels);
    k_csum<<<KCLS, 256>>>();
    k_rowfix<<<NROWS / 8, 256>>>(labels, wp, bp);
    k_main_mma<<<NROWS / 128, 256, SMEM_BYTES>>>(labels, wp, bp, out);
}

// round 6
// speedup vs baseline: 4.7684x; 1.3537x over previous
#include <cuda_runtime.h>
#include <cuda_bf16.h>
#include <math.h>
#include <stdint.h>

#define NROWS 65536
#define DIM   512
#define KCLS  512
#define LISTCAP 768

// -------- scratch (device globals; no runtime allocation) --------
__device__ __nv_bfloat16  g_embh[(size_t)NROWS * DIM];   // normalized embeddings bf16
__device__ float          g_sums[KCLS * DIM];            // per-class sums (fp32, atomic)
__device__ __nv_bfloat16  g_centh[KCLS * DIM];           // centroids bf16 (GEMM B)
__device__ float          g_cnt[KCLS];
__device__ float          g_snorm2[KCLS];
__device__ float          g_rowfix[NROWS];               // exact label-column logit per row
__device__ int            g_ccount[KCLS];
__device__ int            g_lists[KCLS * LISTCAP];

// ================= helpers =================
__device__ __forceinline__ uint32_t smem_u32(const void* p) {
    uint32_t a;
    asm("{ .reg .u64 t; cvta.to.shared.u64 t, %1; cvt.u32.u64 %0, t; }" : "=r"(a) : "l"(p));
    return a;
}
#define CP16(dst, src)  asm volatile("cp.async.cg.shared.global [%0], [%1], 16;" :: "r"(dst), "l"(src) : "memory")
#define CP_COMMIT()     asm volatile("cp.async.commit_group;" ::: "memory")
#define CP_WAIT0()      asm volatile("cp.async.wait_group 0;" ::: "memory")
#define CP_WAIT1()      asm volatile("cp.async.wait_group 1;" ::: "memory")

#define LDSM4(r0, r1, r2, r3, addr)                                           \
    asm volatile("ldmatrix.sync.aligned.m8n8.x4.shared.b16 {%0,%1,%2,%3}, [%4];" \
        : "=r"(r0), "=r"(r1), "=r"(r2), "=r"(r3) : "r"(addr))

#define MMA16816(c, a, b0, b1)                                                \
    asm volatile("mma.sync.aligned.m16n8k16.row.col.f32.bf16.bf16.f32 "       \
        "{%0,%1,%2,%3}, {%4,%5,%6,%7}, {%8,%9}, {%0,%1,%2,%3};"               \
        : "+f"((c)[0]), "+f"((c)[1]), "+f"((c)[2]), "+f"((c)[3])              \
        : "r"((a)[0]), "r"((a)[1]), "r"((a)[2]), "r"((a)[3]), "r"(b0), "r"(b1))

__device__ __forceinline__ float2 bf2f(uint32_t u) {
    __nv_bfloat162 h = *(__nv_bfloat162*)&u;
    return __bfloat1622float2(h);
}

// ================= prep kernels =================
// zero: class counters, class sums (for atomics), output scalar
__global__ void k_zero(float* out) {
    int t = blockIdx.x * blockDim.x + threadIdx.x;
    if (t < KCLS * DIM) g_sums[t] = 0.0f;
    if (t < KCLS) g_ccount[t] = 0;
    if (t == 0) out[0] = 0.0f;
}

// normalize rows -> bf16 only (no fp32 copy)
__global__ void k_norm(const float* __restrict__ x) {
    int row  = blockIdx.x * 8 + (threadIdx.x >> 5);
    int lane = threadIdx.x & 31;
    const float4* src = (const float4*)(x + (size_t)row * DIM);
    float4 v[4];
    float ss = 0.0f;
#pragma unroll
    for (int q = 0; q < 4; q++) {
        v[q] = src[lane + 32 * q];
        ss += v[q].x * v[q].x + v[q].y * v[q].y + v[q].z * v[q].z + v[q].w * v[q].w;
    }
#pragma unroll
    for (int o = 16; o >= 1; o >>= 1) ss += __shfl_xor_sync(0xffffffffu, ss, o);
    float inv = 1.0f / fmaxf(sqrtf(ss), 1e-12f);
    __nv_bfloat162* dsth = (__nv_bfloat162*)(g_embh + (size_t)row * DIM);
#pragma unroll
    for (int q = 0; q < 4; q++) {
        float4 w = v[q];
        w.x *= inv; w.y *= inv; w.z *= inv; w.w *= inv;
        int i = lane + 32 * q;
        dsth[2 * i]     = __floats2bfloat162_rn(w.x, w.y);
        dsth[2 * i + 1] = __floats2bfloat162_rn(w.z, w.w);
    }
}

__global__ void k_lists(const int* __restrict__ labels) {
    int i = blockIdx.x * blockDim.x + threadIdx.x;
    if (i < NROWS) {
        int lab = labels[i];
        int pos = atomicAdd(&g_ccount[lab], 1);
        if (pos < LISTCAP) g_lists[lab * LISTCAP + pos] = i;
    }
}

// class partial sums: grid (KCLS, 4 segments), 256 threads, bf16 gather + fp32 atomics
__global__ void k_csum_part() {
    __shared__ int lst_s[LISTCAP / 4 + 8];
    const int k   = blockIdx.x;
    const int seg = blockIdx.y;
    const int t   = threadIdx.x;              // dims 2t, 2t+1
    const int cnt = g_ccount[k];
    const int s0 = (cnt * seg) >> 2;
    const int s1 = (cnt * (seg + 1)) >> 2;
    const int len = s1 - s0;
    const int* lst = g_lists + k * LISTCAP + s0;
    for (int i = t; i < len; i += 256) lst_s[i] = lst[i];
    __syncthreads();

    float a0 = 0.0f, a1 = 0.0f;
    int m = 0;
    for (; m + 8 <= len; m += 8) {
        uint32_t u[8];
#pragma unroll
        for (int j = 0; j < 8; j++)
            u[j] = *(const uint32_t*)(g_embh + (size_t)lst_s[m + j] * DIM + 2 * t);
#pragma unroll
        for (int j = 0; j < 8; j++) {
            float2 f = bf2f(u[j]);
            a0 += f.x; a1 += f.y;
        }
    }
    for (; m < len; m++) {
        float2 f = bf2f(*(const uint32_t*)(g_embh + (size_t)lst_s[m] * DIM + 2 * t));
        a0 += f.x; a1 += f.y;
    }
    if (len > 0) {
        atomicAdd(&g_sums[k * DIM + 2 * t], a0);
        atomicAdd(&g_sums[k * DIM + 2 * t + 1], a1);
    }
}

// finalize: centroids bf16, counts, ||s||^2
__global__ void k_cfin() {
    int k = blockIdx.x;
    int t = threadIdx.x;
    float a0 = g_sums[k * DIM + t];
    float a1 = g_sums[k * DIM + t + 256];
    float c = (float)g_ccount[k];
    if (t == 0) g_cnt[k] = c;
    float inv = 1.0f / fmaxf(c, 1.0f);
    g_centh[k * DIM + t]       = __float2bfloat16(a0 * inv);
    g_centh[k * DIM + t + 256] = __float2bfloat16(a1 * inv);

    __shared__ float red[256];
    red[t] = a0 * a0 + a1 * a1;
    __syncthreads();
    for (int s = 128; s > 0; s >>= 1) {
        if (t < s) red[t] += red[t + s];
        __syncthreads();
    }
    if (t == 0) g_snorm2[k] = red[0];
}

// exact label-column logit per row (bf16 e, fp32 sums)
__global__ void k_rowfix(const int* __restrict__ labels,
                         const float* __restrict__ wp, const float* __restrict__ bp) {
    int row  = blockIdx.x * 8 + (threadIdx.x >> 5);
    int lane = threadIdx.x & 31;
    int lab = labels[row];
    const uint4*  e4 = (const uint4*)(g_embh + (size_t)row * DIM);
    const float4* s4 = (const float4*)(g_sums + (size_t)lab * DIM);
    float t = 0.0f;
#pragma unroll
    for (int q = 0; q < 2; q++) {
        int u = lane + 32 * q;
        uint4  ev = e4[u];
        float4 sa = s4[2 * u];
        float4 sb = s4[2 * u + 1];
        float2 f0 = bf2f(ev.x), f1 = bf2f(ev.y), f2 = bf2f(ev.z), f3 = bf2f(ev.w);
        t += f0.x * sa.x + f0.y * sa.y + f1.x * sa.z + f1.y * sa.w
           + f2.x * sb.x + f2.y * sb.y + f3.x * sb.z + f3.y * sb.w;
    }
#pragma unroll
    for (int o = 16; o >= 1; o >>= 1) t += __shfl_xor_sync(0xffffffffu, t, o);
    if (lane == 0) {
        float cnt = g_cnt[lab];
        float sn  = g_snorm2[lab];
        float wv = fmaxf(wp[0], 1e-6f);
        float bv = bp[0];
        float simlab;
        if (cnt > 1.0f) {
            float denom = fmaxf(cnt - 1.0f, 1.0f);
            float num = (t - 1.0f) / denom;
            float nrm = sqrtf(fmaxf(sn - 2.0f * t + 1.0f, 0.0f)) / denom;
            simlab = num / fmaxf(nrm, 1e-12f);
        } else {
            simlab = t / fmaxf(cnt, 1.0f);
        }
        g_rowfix[row] = fmaf(wv, simlab, bv);
    }
}

// ================= main: bf16 mma.sync GEMM + fused LSE =================
#define SM_B_OFF 131072
#define SMEM_BYTES (131072 + 2 * 16384)

__global__ void __launch_bounds__(256, 1)
k_main_mma(const int* __restrict__ labels,
           const float* __restrict__ wp, const float* __restrict__ bp,
           float* __restrict__ out) {
    extern __shared__ char smem[];
    const uint32_t smA = smem_u32(smem);
    const uint32_t smB = smA + SM_B_OFF;

    const int tid = threadIdx.x;
    const int wid = tid >> 5;
    const int l   = tid & 31;
    const int wm  = wid >> 1;        // 0..3 (M)
    const int wn  = wid & 1;         // 0..1 (N half)
    const int block_row = blockIdx.x * 128;

    const float wv = fmaxf(wp[0], 1e-6f);
    const float bv = bp[0];

    // ---- load resident A tile (128 x 512 bf16), 16B chunks, XOR swizzle ----
#pragma unroll
    for (int it = 0; it < 32; it++) {
        uint32_t u = it * 256 + tid;
        uint32_t r = u >> 6, ch = u & 63;
        CP16(smA + r * 1024 + ((ch ^ (r & 7)) << 4),
             g_embh + (size_t)(block_row + r) * DIM + ch * 8);
    }
    CP_COMMIT();

    // ---- per-thread row metadata ----
    int lab_[2][2];
    float rf_[2][2];
#pragma unroll
    for (int mt = 0; mt < 2; mt++)
#pragma unroll
        for (int h = 0; h < 2; h++) {
            int rr = block_row + wm * 32 + mt * 16 + (l >> 2) + h * 8;
            lab_[mt][h] = labels[rr];
            rf_[mt][h]  = g_rowfix[rr];
        }

    float run_m[2][2], run_s[2][2];
#pragma unroll
    for (int mt = 0; mt < 2; mt++)
#pragma unroll
        for (int h = 0; h < 2; h++) { run_m[mt][h] = -INFINITY; run_s[mt][h] = 0.0f; }

    for (int chunk = 0; chunk < 4; chunk++) {
        const int c0 = chunk * 128;

#pragma unroll
        for (int it = 0; it < 4; it++) {
            uint32_t u = it * 256 + tid;
            uint32_t nr = u >> 3, k16 = u & 7;
            CP16(smB + nr * 128 + ((k16 ^ (nr & 7)) << 4),
                 g_centh + (size_t)(c0 + nr) * DIM + k16 * 8);
        }
        CP_COMMIT();

        float acc[2][8][4];
#pragma unroll
        for (int mt = 0; mt < 2; mt++)
#pragma unroll
            for (int nt = 0; nt < 8; nt++)
#pragma unroll
                for (int c = 0; c < 4; c++) acc[mt][nt][c] = 0.0f;

        for (int kb = 0; kb < 8; kb++) {
            const uint32_t buf = (uint32_t)(kb & 1);
            if (kb < 7) {
                const uint32_t nb = buf ^ 1;
#pragma unroll
                for (int it = 0; it < 4; it++) {
                    uint32_t u = it * 256 + tid;
                    uint32_t nr = u >> 3, k16 = u & 7;
                    CP16(smB + nb * 16384 + nr * 128 + ((k16 ^ (nr & 7)) << 4),
                         g_centh + (size_t)(c0 + nr) * DIM + (kb + 1) * 64 + k16 * 8);
                }
                CP_COMMIT();
                CP_WAIT1();
            } else {
                CP_WAIT0();
            }
            __syncthreads();

#pragma unroll
            for (int step = 0; step < 4; step++) {
                uint32_t a[2][4];
#pragma unroll
                for (int mt = 0; mt < 2; mt++) {
                    uint32_t r = wm * 32 + mt * 16 + (l & 15);
                    uint32_t chA = kb * 8 + step * 2 + (l >> 4);
                    LDSM4(a[mt][0], a[mt][1], a[mt][2], a[mt][3],
                          smA + r * 1024 + ((chA ^ (r & 7)) << 4));
                }
                uint32_t bf[8][2];
#pragma unroll
                for (int np = 0; np < 4; np++) {
                    uint32_t n = wn * 64 + np * 16 + (l & 7) + ((l >> 4) & 1) * 8;
                    uint32_t chB = step * 2 + ((l >> 3) & 1);
                    uint32_t r0, r1, r2, r3;
                    LDSM4(r0, r1, r2, r3,
                          smB + buf * 16384 + n * 128 + ((chB ^ (n & 7)) << 4));
                    bf[2 * np][0] = r0;     bf[2 * np][1] = r1;
                    bf[2 * np + 1][0] = r2; bf[2 * np + 1][1] = r3;
                }
#pragma unroll
                for (int mt = 0; mt < 2; mt++)
#pragma unroll
                    for (int nt = 0; nt < 8; nt++)
                        MMA16816(acc[mt][nt], a[mt], bf[nt][0], bf[nt][1]);
            }
            __syncthreads();
        }

        // ---- chunk epilogue: per-row LSE over this warp's 64 cols ----
#pragma unroll
        for (int mt = 0; mt < 2; mt++) {
#pragma unroll
            for (int h = 0; h < 2; h++) {
                float v[16];
                float cm = -INFINITY;
#pragma unroll
                for (int nt = 0; nt < 8; nt++)
#pragma unroll
                    for (int cc = 0; cc < 2; cc++) {
                        int col = c0 + wn * 64 + nt * 8 + ((l & 3) << 1) + cc;
                        float raw = acc[mt][nt][h * 2 + cc];
                        float lg = (col == lab_[mt][h]) ? rf_[mt][h]
                                                        : fmaf(wv, raw, bv);
                        v[nt * 2 + cc] = lg;
                        cm = fmaxf(cm, lg);
                    }
#pragma unroll
                for (int o = 1; o <= 2; o <<= 1)
                    cm = fmaxf(cm, __shfl_xor_sync(0xffffffffu, cm, o));
                float cs = 0.0f;
#pragma unroll
                for (int j = 0; j < 16; j++) cs += __expf(v[j] - cm);
#pragma unroll
                for (int o = 1; o <= 2; o <<= 1)
                    cs += __shfl_xor_sync(0xffffffffu, cs, o);
                float mo = run_m[mt][h];
                float mn = fmaxf(mo, cm);
                run_s[mt][h] = run_s[mt][h] * __expf(mo - mn) + cs * __expf(cm - mn);
                run_m[mt][h] = mn;
            }
        }
    }

    // ---- merge the two N-half warps per row, compute loss ----
    __syncthreads();
    float* marr = (float*)smem;          // reuse A region (dead now)
    float* sarr = marr + 128;
    if (wn == 0 && (l & 3) == 0) {
#pragma unroll
        for (int mt = 0; mt < 2; mt++)
#pragma unroll
            for (int h = 0; h < 2; h++) {
                int rr = wm * 32 + mt * 16 + h * 8 + (l >> 2);
                marr[rr] = run_m[mt][h];
                sarr[rr] = run_s[mt][h];
            }
    }
    __syncthreads();
    float loss = 0.0f;
    if (wn == 1 && (l & 3) == 0) {
#pragma unroll
        for (int mt = 0; mt < 2; mt++)
#pragma unroll
            for (int h = 0; h < 2; h++) {
                int rr = wm * 32 + mt * 16 + h * 8 + (l >> 2);
                float m0 = marr[rr], s0 = sarr[rr];
                float m1 = run_m[mt][h], s1 = run_s[mt][h];
                float mn = fmaxf(m0, m1);
                float ssum = s0 * __expf(m0 - mn) + s1 * __expf(m1 - mn);
                loss += mn + logf(ssum) - rf_[mt][h];
            }
    }
#pragma unroll
    for (int o = 16; o >= 1; o >>= 1) loss += __shfl_xor_sync(0xffffffffu, loss, o);
    if (wn == 1 && l == 0) atomicAdd(out, loss * (1.0f / (float)NROWS));
}

extern "C" void kernel_launch(void* const* d_in, const int* in_sizes, int n_in,
                              void* d_out, int out_size) {
    const float* emb    = (const float*)d_in[0];
    const int*   labels = (const int*)d_in[1];
    const float* wp     = (const float*)d_in[2];
    const float* bp     = (const float*)d_in[3];
    float* out = (float*)d_out;

    cudaFuncSetAttribute(k_main_mma, cudaFuncAttributeMaxDynamicSharedMemorySize, SMEM_BYTES);

    k_zero<<<(KCLS * DIM) / 256, 256>>>(out);
    k_norm<<<NROWS / 8, 256>>>(emb);
    k_lists<<<NROWS / 256, 256>>>(labels);
    k_csum_part<<<dim3(KCLS, 4), 256>>>();
    k_cfin<<<KCLS, 256>>>();
    k_rowfix<<<NROWS / 8, 256>>>(labels, wp, bp);
    k_main_mma<<<NROWS / 128, 256, SMEM_BYTES>>>(labels, wp, bp, out);
}